// round 9
// baseline (speedup 1.0000x reference)
#include <cuda_runtime.h>
#include <cstdint>

#define B        4
#define T        1024
#define HALF     256      // VALUE_DIM / 2
#define C        256
#define NLAB     64
#define VDIM     512

#define NBLK     256      // 64 labels x 4 d-chunks; must be co-resident
#define NTHR     256

// Scratch A[b][l][d] (65536 floats). Invariant: zero at entry to every launch
// (static zero-init; contract phase consume-and-clears its exclusive slice).
__device__ float g_A[B * NLAB * HALF];

// Sense-reversing grid barrier (sense increments once per launch; count resets).
__device__ unsigned int          g_bar_count;
__device__ volatile unsigned int g_bar_sense;

__device__ __forceinline__ void grid_barrier() {
    __syncthreads();
    __threadfence();                       // publish scatter atomics / out zeros
    if (threadIdx.x == 0) {
        unsigned int sense = g_bar_sense;
        unsigned int t = atomicAdd(&g_bar_count, 1u);
        if (t == (unsigned)(NBLK - 1)) {
            atomicExch(&g_bar_count, 0u);
            __threadfence();
            g_bar_sense = sense + 1u;      // release
        } else {
            while (g_bar_sense == sense) { }
        }
    }
    __syncthreads();
    __threadfence();                       // acquire side
}

__device__ __forceinline__ void fma4(float4& acc, float a, const float4& w) {
    acc.x += a * w.x; acc.y += a * w.y; acc.z += a * w.z; acc.w += a * w.w;
}

// ---------------------------------------------------------------------------
// Fused: [zero out] + scatter  ||grid barrier||  contract -> out atomics
// ---------------------------------------------------------------------------
__global__ void __launch_bounds__(NTHR)
vb_fused_kernel(const int*   __restrict__ indices,
                const float* __restrict__ scores,
                const float* __restrict__ W,
                const int*   __restrict__ label,
                const int*   __restrict__ index_p,
                const float* __restrict__ weight,
                float*       __restrict__ out) {
    __shared__ float  sA[B][64];
    __shared__ float4 s_part[3][64][B];   // dgrp 1..3 partials (12 KB)

    const int tid = threadIdx.x;
    const int bid = blockIdx.x;
    const int off = (*index_p == 1) ? HALF : 0;

    // --- zero the (poisoned) output ----------------------------------------
    if (bid < B) out[bid * C + tid] = 0.0f;

    // --- Phase A: scatter-accumulate, 2 tokens per warp ---------------------
    {
        const int gw   = bid * (NTHR / 32) + (tid >> 5);
        const int lane = tid & 31;
#pragma unroll
        for (int r = 0; r < 2; r++) {
            const int tok = gw * 2 + r;            // 0 .. B*T-1
            const int   idx = indices[tok];        // warp-uniform
            const float sc  = scores[tok];
            const int   lab = label[tok];
            const int   b   = tok >> 10;           // tok = b*T + t

            const float4* wrow = reinterpret_cast<const float4*>(
                weight + (size_t)idx * VDIM + off);
            float4 v0 = __ldg(wrow + lane);
            float4 v1 = __ldg(wrow + lane + 32);
            v0.x *= sc; v0.y *= sc; v0.z *= sc; v0.w *= sc;
            v1.x *= sc; v1.y *= sc; v1.z *= sc; v1.w *= sc;

            float4* dst = reinterpret_cast<float4*>(
                g_A + (size_t)(b * NLAB + lab) * HALF);
            atomicAdd(dst + lane,      v0);
            atomicAdd(dst + lane + 32, v1);
        }
    }

    grid_barrier();

    // --- Phase B: contraction (R8 shape) ------------------------------------
    // Block (l, ch): l = bid>>2, ch = bid&3 (64 d's).
    // Thread: c4 = tid&63 (4 output cols), dgrp = tid>>6 (16 d's).
    const int l    = bid >> 2;
    const int ch   = bid & 3;
    const int c4   = tid & 63;
    const int dgrp = tid >> 6;

    // Stage A slice and clear it (exclusive ownership -> race-free).
    {
        const int b  = tid >> 6;
        const int dd = tid & 63;
        float* ap = &g_A[(size_t)(b * NLAB + l) * HALF + ch * 64 + dd];
        sA[b][dd] = __ldcg(ap);
        *ap = 0.0f;                       // restore zero invariant for next replay
    }
    __syncthreads();

    const float4* Wp = reinterpret_cast<const float4*>(
        W + ((size_t)l * VDIM + off + ch * 64 + dgrp * 16) * C) + c4;

    float4 acc0 = {0,0,0,0}, acc1 = {0,0,0,0}, acc2 = {0,0,0,0}, acc3 = {0,0,0,0};

#pragma unroll
    for (int h = 0; h < 2; h++) {
        float4 w[8];
#pragma unroll
        for (int i = 0; i < 8; i++)                 // 8 LDG.128 in flight
            w[i] = __ldg(Wp + (size_t)(h * 8 + i) * (C / 4));
#pragma unroll
        for (int i = 0; i < 8; i++) {
            const int d = dgrp * 16 + h * 8 + i;
            fma4(acc0, sA[0][d], w[i]);
            fma4(acc1, sA[1][d], w[i]);
            fma4(acc2, sA[2][d], w[i]);
            fma4(acc3, sA[3][d], w[i]);
        }
    }

    if (dgrp > 0) {
        s_part[dgrp - 1][c4][0] = acc0;
        s_part[dgrp - 1][c4][1] = acc1;
        s_part[dgrp - 1][c4][2] = acc2;
        s_part[dgrp - 1][c4][3] = acc3;
    }
    __syncthreads();

    if (dgrp == 0) {
#pragma unroll
        for (int k = 0; k < 3; k++) {
            const float4 p0 = s_part[k][c4][0];
            const float4 p1 = s_part[k][c4][1];
            const float4 p2 = s_part[k][c4][2];
            const float4 p3 = s_part[k][c4][3];
            acc0.x += p0.x; acc0.y += p0.y; acc0.z += p0.z; acc0.w += p0.w;
            acc1.x += p1.x; acc1.y += p1.y; acc1.z += p1.z; acc1.w += p1.w;
            acc2.x += p2.x; acc2.y += p2.y; acc2.z += p2.z; acc2.w += p2.w;
            acc3.x += p3.x; acc3.y += p3.y; acc3.z += p3.z; acc3.w += p3.w;
        }
        float4* o = reinterpret_cast<float4*>(out) + c4;
        atomicAdd(o,               acc0);
        atomicAdd(o + 1 * (C / 4), acc1);
        atomicAdd(o + 2 * (C / 4), acc2);
        atomicAdd(o + 3 * (C / 4), acc3);
    }
}

// ---------------------------------------------------------------------------
// Inputs (metadata order):
//   0: indices (B,T) int32     1: scores (B,T) f32
//   2: W (64,512,256) f32      3: label (B,T) int32
//   4: index scalar int32      5: weight (262144,512) f32
// Output: (B, C) f32 = 1024 floats
// ---------------------------------------------------------------------------
extern "C" void kernel_launch(void* const* d_in, const int* in_sizes, int n_in,
                              void* d_out, int out_size) {
    const int*   indices = (const int*)  d_in[0];
    const float* scores  = (const float*)d_in[1];
    const float* W       = (const float*)d_in[2];
    const int*   label   = (const int*)  d_in[3];
    const int*   index_p = (const int*)  d_in[4];
    const float* weight  = (const float*)d_in[5];
    float*       out     = (float*)d_out;

    vb_fused_kernel<<<NBLK, NTHR>>>(indices, scores, W, label, index_p,
                                    weight, out);
}